// round 9
// baseline (speedup 1.0000x reference)
#include <cuda_runtime.h>
#include <cuda_bf16.h>

// LocalFeatureAggregation: B=4, N=16384, K=16, C=64, D=64
// out[p, 0:64]   = mean_k leaky( geom[p,k,:] @ w^T + b )
// out[p, 64:128] = mean_k features[b, idx[p,k], :]
//
// One warp per point, k split across half-warps (exact: mean over k is additive).
//  MLP:   half-warp h handles k = 2s+h (s=0..7). Lane (h,c) owns channels
//         {c, c+32} and {c+16, c+48} as two packed f32x2 pairs. Final
//         shfl_xor(16) combines the k-halves.
//  Gather: 8 LDG.128 (two rows per instruction); indices via one distinct
//         LDG.32 + per-step shfl.idx (off the L1 writeback path).
//  __launch_bounds__(256, 6): cap regs ~42 -> 48 warps/SM (was 64 regs/43.9%).

#define KNB 16
#define FULLMASK 0xffffffffu

__device__ __forceinline__ unsigned long long pk2(float x, float y) {
    unsigned long long r;
    asm("mov.b64 %0, {%1,%2};" : "=l"(r) : "f"(x), "f"(y));
    return r;
}
__device__ __forceinline__ void upk2(unsigned long long v, float& x, float& y) {
    asm("mov.b64 {%0,%1}, %2;" : "=f"(x), "=f"(y) : "l"(v));
}
__device__ __forceinline__ unsigned long long fma2(unsigned long long a,
                                                   unsigned long long b,
                                                   unsigned long long c) {
    unsigned long long d;
    asm("fma.rn.f32x2 %0, %1, %2, %3;" : "=l"(d) : "l"(a), "l"(b), "l"(c));
    return d;
}
__device__ __forceinline__ unsigned long long add2(unsigned long long a,
                                                   unsigned long long b) {
    unsigned long long d;
    asm("add.rn.f32x2 %0, %1, %2;" : "=l"(d) : "l"(a), "l"(b));
    return d;
}
__device__ __forceinline__ unsigned long long mul2(unsigned long long a,
                                                   unsigned long long b) {
    unsigned long long d;
    asm("mul.rn.f32x2 %0, %1, %2;" : "=l"(d) : "l"(a), "l"(b));
    return d;
}
__device__ __forceinline__ unsigned long long shflxor16(unsigned long long v) {
    unsigned lo = (unsigned)v, hi = (unsigned)(v >> 32);
    lo = __shfl_xor_sync(FULLMASK, lo, 16);
    hi = __shfl_xor_sync(FULLMASK, hi, 16);
    return ((unsigned long long)hi << 32) | lo;
}

__global__ __launch_bounds__(256, 6) void lfa_kernel(
    const float* __restrict__ features,       // [B, N, 64]
    const float4* __restrict__ geom4,         // [B*N*16] float4 (k-major)
    const float* __restrict__ w,              // [64, 4]
    const float* __restrict__ bias,           // [64]
    const int* __restrict__ nbr,              // [B, N, 16] int32
    float* __restrict__ out,                  // [B, N, 128]
    int points, int n_log2)
{
    __shared__ float4 ws[64];
    __shared__ float  bs[64];

    const int tid = threadIdx.x;
    if (tid < 64) {
        ws[tid] = ((const float4*)w)[tid];
        bs[tid] = bias[tid];
    }
    __syncthreads();

    const int warp = tid >> 5;
    const int lane = tid & 31;
    const int p = blockIdx.x * 8 + warp;
    if (p >= points) return;                          // uniform per warp

    const int h = lane >> 4;            // half-warp id
    const int c = lane & 15;

    // ---- neighbor indices: distinct LDG.32 (64B), delivered later via shfl ----
    const int myidx = nbr[(size_t)p * KNB + c];

    // ---- per-lane packed weight/bias pairs for {c,c+32} and {c+16,c+48} ----
    unsigned long long w00, w01, w02, w03, w10, w11, w12, w13, bP0, bP1;
    {
        const float4 a0 = ws[c],      b0 = ws[c + 32];
        const float4 a1 = ws[c + 16], b1 = ws[c + 48];
        w00 = pk2(a0.x, b0.x); w01 = pk2(a0.y, b0.y);
        w02 = pk2(a0.z, b0.z); w03 = pk2(a0.w, b0.w);
        w10 = pk2(a1.x, b1.x); w11 = pk2(a1.y, b1.y);
        w12 = pk2(a1.z, b1.z); w13 = pk2(a1.w, b1.w);
        bP0 = pk2(bs[c], bs[c + 32]);
        bP1 = pk2(bs[c + 16], bs[c + 48]);
    }
    const unsigned long long c055 = pk2(0.55f, 0.55f);
    const unsigned long long c045 = pk2(0.45f, 0.45f);
    const unsigned long long ABSM = 0x7fffffff7fffffffULL;

    const int bIdx = p >> n_log2;
    const int nPerB = 1 << n_log2;
    const ulonglong2* featq =
        (const ulonglong2*)(features + (size_t)bIdx * nPerB * 64) + c;
    const float4* gpt = geom4 + (size_t)p * KNB;

    unsigned long long accP0 = 0ull, accP1 = 0ull;   // MLP partial (this k-half)
    unsigned long long gx = 0ull, gy = 0ull;         // gather acc

#pragma unroll
    for (int s = 0; s < 8; s++) {
        // geometry for this half's k = 2s+h: one LDG.128, 2 distinct 16B addrs
        const float4 v = gpt[2 * s + h];

        // gather row idx[2s+h] (index via shuffle, not L1)
        const int r = __shfl_sync(FULLMASK, myidx, 2 * s + h);
        const ulonglong2 fv = featq[(size_t)r * 16];
        gx = add2(gx, fv.x);
        gy = add2(gy, fv.y);

        // MLP for k = 2s+h, two packed channel pairs
        const unsigned long long g0 = pk2(v.x, v.x);
        const unsigned long long g1 = pk2(v.y, v.y);
        const unsigned long long g2 = pk2(v.z, v.z);
        const unsigned long long g3 = pk2(v.w, v.w);

        unsigned long long t0 = fma2(g0, w00, bP0);
        t0 = fma2(g1, w01, t0); t0 = fma2(g2, w02, t0); t0 = fma2(g3, w03, t0);
        accP0 = fma2(t0, c055, accP0);
        accP0 = fma2(t0 & ABSM, c045, accP0);

        unsigned long long t1 = fma2(g0, w10, bP1);
        t1 = fma2(g1, w11, t1); t1 = fma2(g2, w12, t1); t1 = fma2(g3, w13, t1);
        accP1 = fma2(t1, c055, accP1);
        accP1 = fma2(t1 & ABSM, c045, accP1);
    }

    // ---- combine k-halves and write MLP output ----
    const unsigned long long inv = pk2(0.0625f, 0.0625f);
    accP0 = mul2(add2(accP0, shflxor16(accP0)), inv);
    accP1 = mul2(add2(accP1, shflxor16(accP1)), inv);

    float p0l, p0h, p1l, p1h;
    upk2(accP0, p0l, p0h);        // (ch c, ch c+32)
    upk2(accP1, p1l, p1h);        // (ch c+16, ch c+48)

    const size_t ob = (size_t)p * 128;
    // half 0 writes {c, c+16}; half 1 writes {c+32, c+48}
    float* o0 = out + ob + c + 32 * h;
    o0[0]  = h ? p0h : p0l;
    o0[16] = h ? p1h : p1l;

    // ---- combine gather halves, write [64,128) ----
    const unsigned long long ox = __shfl_down_sync(FULLMASK, gx, 16);
    const unsigned long long oy = __shfl_down_sync(FULLMASK, gy, 16);
    if (lane < 16) {
        ulonglong2 res;
        res.x = mul2(add2(gx, ox), inv);
        res.y = mul2(add2(gy, oy), inv);
        ((ulonglong2*)(out + ob + 64))[c] = res;
    }
}

extern "C" void kernel_launch(void* const* d_in, const int* in_sizes, int n_in,
                              void* d_out, int out_size) {
    const float* features    = (const float*)d_in[0];
    const float* geom        = (const float*)d_in[1];
    const float* w           = (const float*)d_in[2];
    const float* bias        = (const float*)d_in[3];
    const int*   nbr         = (const int*)d_in[4];    // int32 (JAX x64 off)
    float* out               = (float*)d_out;

    const int points = in_sizes[0] / 64;          // B*N = 65536
    const int n_log2 = 14;                        // N = 16384 per batch

    const int blocks = (points + 7) / 8;
    (void)n_in; (void)out_size;
    lfa_kernel<<<blocks, 256>>>(features, (const float4*)geom, w, bias, nbr,
                                out, points, n_log2);
}

// round 10
// speedup vs baseline: 1.8499x; 1.8499x over previous
#include <cuda_runtime.h>
#include <cuda_bf16.h>

// LocalFeatureAggregation: B=4, N=16384, K=16, C=64, D=64
// out[p, 0:64]   = mean_k leaky( geom[p,k,:] @ w^T + b )    <- lfa_mlp
// out[p, 64:128] = mean_k features[b, idx[p,k], :]          <- lfa_gather
//
// Split into two kernels so each fits its natural register budget (the fused
// version needed 64 regs -> 43.9% occ; capping to 40 spilled and ran 2x slower).
//
// Both kernels: one warp per point, k split across half-warps (exact: mean
// over k is additive). Math identical to the verified fused kernel.

#define KNB 16
#define FULLMASK 0xffffffffu

__device__ __forceinline__ unsigned long long pk2(float x, float y) {
    unsigned long long r;
    asm("mov.b64 %0, {%1,%2};" : "=l"(r) : "f"(x), "f"(y));
    return r;
}
__device__ __forceinline__ void upk2(unsigned long long v, float& x, float& y) {
    asm("mov.b64 {%0,%1}, %2;" : "=f"(x), "=f"(y) : "l"(v));
}
__device__ __forceinline__ unsigned long long fma2(unsigned long long a,
                                                   unsigned long long b,
                                                   unsigned long long c) {
    unsigned long long d;
    asm("fma.rn.f32x2 %0, %1, %2, %3;" : "=l"(d) : "l"(a), "l"(b), "l"(c));
    return d;
}
__device__ __forceinline__ unsigned long long add2(unsigned long long a,
                                                   unsigned long long b) {
    unsigned long long d;
    asm("add.rn.f32x2 %0, %1, %2;" : "=l"(d) : "l"(a), "l"(b));
    return d;
}
__device__ __forceinline__ unsigned long long mul2(unsigned long long a,
                                                   unsigned long long b) {
    unsigned long long d;
    asm("mul.rn.f32x2 %0, %1, %2;" : "=l"(d) : "l"(a), "l"(b));
    return d;
}
__device__ __forceinline__ unsigned long long shflxor16(unsigned long long v) {
    unsigned lo = (unsigned)v, hi = (unsigned)(v >> 32);
    lo = __shfl_xor_sync(FULLMASK, lo, 16);
    hi = __shfl_xor_sync(FULLMASK, hi, 16);
    return ((unsigned long long)hi << 32) | lo;
}

// ---------------- kernel 1: MLP branch, channels [0,64) ----------------
__global__ __launch_bounds__(256) void lfa_mlp(
    const float4* __restrict__ geom4,         // [B*N*16] float4 (k-major)
    const float* __restrict__ w,              // [64, 4]
    const float* __restrict__ bias,           // [64]
    float* __restrict__ out,                  // [B, N, 128]
    int points)
{
    __shared__ float4 ws[64];
    __shared__ float  bs[64];

    const int tid = threadIdx.x;
    if (tid < 64) {
        ws[tid] = ((const float4*)w)[tid];
        bs[tid] = bias[tid];
    }
    __syncthreads();

    const int warp = tid >> 5;
    const int lane = tid & 31;
    const int p = blockIdx.x * 8 + warp;
    if (p >= points) return;

    const int h = lane >> 4;            // half-warp: k parity
    const int c = lane & 15;

    // packed weight/bias pairs for channel pairs {c,c+32} and {c+16,c+48}
    unsigned long long w00, w01, w02, w03, w10, w11, w12, w13, bP0, bP1;
    {
        const float4 a0 = ws[c],      b0 = ws[c + 32];
        const float4 a1 = ws[c + 16], b1 = ws[c + 48];
        w00 = pk2(a0.x, b0.x); w01 = pk2(a0.y, b0.y);
        w02 = pk2(a0.z, b0.z); w03 = pk2(a0.w, b0.w);
        w10 = pk2(a1.x, b1.x); w11 = pk2(a1.y, b1.y);
        w12 = pk2(a1.z, b1.z); w13 = pk2(a1.w, b1.w);
        bP0 = pk2(bs[c], bs[c + 32]);
        bP1 = pk2(bs[c + 16], bs[c + 48]);
    }
    const unsigned long long c055 = pk2(0.55f, 0.55f);
    const unsigned long long c045 = pk2(0.45f, 0.45f);
    const unsigned long long ABSM = 0x7fffffff7fffffffULL;

    const float4* gpt = geom4 + (size_t)p * KNB;

    unsigned long long accP0 = 0ull, accP1 = 0ull;

#pragma unroll
    for (int s = 0; s < 8; s++) {
        // k = 2s+h: one LDG.128, two distinct 16B addrs per warp
        const float4 v = gpt[2 * s + h];

        const unsigned long long g0 = pk2(v.x, v.x);
        const unsigned long long g1 = pk2(v.y, v.y);
        const unsigned long long g2 = pk2(v.z, v.z);
        const unsigned long long g3 = pk2(v.w, v.w);

        unsigned long long t0 = fma2(g0, w00, bP0);
        t0 = fma2(g1, w01, t0); t0 = fma2(g2, w02, t0); t0 = fma2(g3, w03, t0);
        accP0 = fma2(t0, c055, accP0);
        accP0 = fma2(t0 & ABSM, c045, accP0);

        unsigned long long t1 = fma2(g0, w10, bP1);
        t1 = fma2(g1, w11, t1); t1 = fma2(g2, w12, t1); t1 = fma2(g3, w13, t1);
        accP1 = fma2(t1, c055, accP1);
        accP1 = fma2(t1 & ABSM, c045, accP1);
    }

    const unsigned long long inv = pk2(0.0625f, 0.0625f);
    accP0 = mul2(add2(accP0, shflxor16(accP0)), inv);
    accP1 = mul2(add2(accP1, shflxor16(accP1)), inv);

    float p0l, p0h, p1l, p1h;
    upk2(accP0, p0l, p0h);        // (ch c,    ch c+32)
    upk2(accP1, p1l, p1h);        // (ch c+16, ch c+48)

    float* o0 = out + (size_t)p * 128 + c + 32 * h;
    o0[0]  = h ? p0h : p0l;       // ch c+32h
    o0[16] = h ? p1h : p1l;       // ch c+16+32h
}

// ---------------- kernel 2: gather branch, channels [64,128) ----------------
__global__ __launch_bounds__(256) void lfa_gather(
    const float* __restrict__ features,       // [B, N, 64]
    const int* __restrict__ nbr,              // [B, N, 16] int32
    float* __restrict__ out,                  // [B, N, 128]
    int points, int n_log2)
{
    const int tid = threadIdx.x;
    const int warp = tid >> 5;
    const int lane = tid & 31;
    const int p = blockIdx.x * 8 + warp;
    if (p >= points) return;

    const int h = lane >> 4;
    const int c = lane & 15;

    const int myidx = nbr[(size_t)p * KNB + c];   // lanes 16-31 mirror 0-15

    const int bIdx = p >> n_log2;
    const int nPerB = 1 << n_log2;
    const ulonglong2* featq =
        (const ulonglong2*)(features + (size_t)bIdx * nPerB * 64) + c;

    unsigned long long gx = 0ull, gy = 0ull;

#pragma unroll
    for (int s = 0; s < 8; s++) {
        const int r = __shfl_sync(FULLMASK, myidx, 2 * s + h);
        const ulonglong2 fv = featq[(size_t)r * 16];   // row stride 256B
        gx = add2(gx, fv.x);
        gy = add2(gy, fv.y);
    }

    const unsigned long long ox = __shfl_down_sync(FULLMASK, gx, 16);
    const unsigned long long oy = __shfl_down_sync(FULLMASK, gy, 16);
    if (lane < 16) {
        const unsigned long long inv = pk2(0.0625f, 0.0625f);
        ulonglong2 res;
        res.x = mul2(add2(gx, ox), inv);
        res.y = mul2(add2(gy, oy), inv);
        ((ulonglong2*)(out + (size_t)p * 128 + 64))[c] = res;
    }
}

extern "C" void kernel_launch(void* const* d_in, const int* in_sizes, int n_in,
                              void* d_out, int out_size) {
    const float* features    = (const float*)d_in[0];
    const float* geom        = (const float*)d_in[1];
    const float* w           = (const float*)d_in[2];
    const float* bias        = (const float*)d_in[3];
    const int*   nbr         = (const int*)d_in[4];    // int32 (JAX x64 off)
    float* out               = (float*)d_out;

    const int points = in_sizes[0] / 64;          // B*N = 65536
    const int n_log2 = 14;                        // N = 16384 per batch
    const int blocks = (points + 7) / 8;

    (void)n_in; (void)out_size;
    lfa_gather<<<blocks, 256>>>(features, nbr, out, points, n_log2);
    lfa_mlp<<<blocks, 256>>>((const float4*)geom, w, bias, out, points);
}

// round 13
// speedup vs baseline: 2.0718x; 1.1200x over previous
#include <cuda_runtime.h>
#include <cuda_bf16.h>

// LocalFeatureAggregation: B=4, N=16384, K=16, C=64, D=64
// out[p, 0:64]   = mean_k leaky( geom[p,k,:] @ w^T + b )
// out[p, 64:128] = mean_k features[b, idx[p,k], :]
//
// Fused, one warp per point, k split across half-warps (mean over k additive).
//  MLP:   half-warp h handles k = 2s+h. Lane (h,c) owns channel pairs
//         {c,c+32} and {c+16,c+48} as packed f32x2. shfl_xor(16) combines.
//  Gather: 8 LDG.128 (two rows/instr); indices via LDG.32 + per-step shfl.
//  #pragma unroll 2 keeps only ~2+2 loads in flight -> fewer live registers
//  (full unroll batches 8 loads -> 58-64 regs -> 43% occ).
//  128-thread blocks for finer occupancy granularity. No launch_bounds cap
//  (forced caps spill and run 2x slower).

#define KNB 16
#define FULLMASK 0xffffffffu

__device__ __forceinline__ unsigned long long pk2(float x, float y) {
    unsigned long long r;
    asm("mov.b64 %0, {%1,%2};" : "=l"(r) : "f"(x), "f"(y));
    return r;
}
__device__ __forceinline__ void upk2(unsigned long long v, float& x, float& y) {
    asm("mov.b64 {%0,%1}, %2;" : "=f"(x), "=f"(y) : "l"(v));
}
__device__ __forceinline__ unsigned long long fma2(unsigned long long a,
                                                   unsigned long long b,
                                                   unsigned long long c) {
    unsigned long long d;
    asm("fma.rn.f32x2 %0, %1, %2, %3;" : "=l"(d) : "l"(a), "l"(b), "l"(c));
    return d;
}
__device__ __forceinline__ unsigned long long add2(unsigned long long a,
                                                   unsigned long long b) {
    unsigned long long d;
    asm("add.rn.f32x2 %0, %1, %2;" : "=l"(d) : "l"(a), "l"(b));
    return d;
}
__device__ __forceinline__ unsigned long long mul2(unsigned long long a,
                                                   unsigned long long b) {
    unsigned long long d;
    asm("mul.rn.f32x2 %0, %1, %2;" : "=l"(d) : "l"(a), "l"(b));
    return d;
}
__device__ __forceinline__ unsigned long long shflxor16(unsigned long long v) {
    unsigned lo = (unsigned)v, hi = (unsigned)(v >> 32);
    lo = __shfl_xor_sync(FULLMASK, lo, 16);
    hi = __shfl_xor_sync(FULLMASK, hi, 16);
    return ((unsigned long long)hi << 32) | lo;
}

__global__ void lfa_kernel(
    const float* __restrict__ features,       // [B, N, 64]
    const float4* __restrict__ geom4,         // [B*N*16] float4 (k-major)
    const float* __restrict__ w,              // [64, 4]
    const float* __restrict__ bias,           // [64]
    const int* __restrict__ nbr,              // [B, N, 16] int32
    float* __restrict__ out,                  // [B, N, 128]
    int points, int n_log2)
{
    __shared__ float4 ws[64];
    __shared__ float  bs[64];

    const int tid = threadIdx.x;
    if (tid < 64) {
        ws[tid] = ((const float4*)w)[tid];
        bs[tid] = bias[tid];
    }
    __syncthreads();

    const int warp = tid >> 5;
    const int lane = tid & 31;
    const int p = blockIdx.x * 4 + warp;
    if (p >= points) return;                  // uniform per warp

    const int h = lane >> 4;            // half-warp id (k parity)
    const int c = lane & 15;

    // ---- neighbor indices: distinct LDG.32 (64B), delivered via shfl ----
    const int myidx = nbr[(size_t)p * KNB + c];

    // ---- per-lane packed weight/bias pairs for {c,c+32} and {c+16,c+48} ----
    unsigned long long w00, w01, w02, w03, w10, w11, w12, w13, bP0, bP1;
    {
        const float4 a0 = ws[c],      b0 = ws[c + 32];
        const float4 a1 = ws[c + 16], b1 = ws[c + 48];
        w00 = pk2(a0.x, b0.x); w01 = pk2(a0.y, b0.y);
        w02 = pk2(a0.z, b0.z); w03 = pk2(a0.w, b0.w);
        w10 = pk2(a1.x, b1.x); w11 = pk2(a1.y, b1.y);
        w12 = pk2(a1.z, b1.z); w13 = pk2(a1.w, b1.w);
        bP0 = pk2(bs[c], bs[c + 32]);
        bP1 = pk2(bs[c + 16], bs[c + 48]);
    }
    const unsigned long long c055 = pk2(0.55f, 0.55f);
    const unsigned long long c045 = pk2(0.45f, 0.45f);
    const unsigned long long ABSM = 0x7fffffff7fffffffULL;

    const int bIdx = p >> n_log2;
    const int nPerB = 1 << n_log2;
    const ulonglong2* featq =
        (const ulonglong2*)(features + (size_t)bIdx * nPerB * 64) + c;
    const float4* gpt = geom4 + (size_t)p * KNB;

    unsigned long long accP0 = 0ull, accP1 = 0ull;   // MLP partial (this k-half)
    unsigned long long gx = 0ull, gy = 0ull;         // gather acc

#pragma unroll 2
    for (int s = 0; s < 8; s++) {
        // geometry for this half's k = 2s+h: one LDG.128, 2 distinct 16B addrs
        const float4 v = gpt[2 * s + h];

        // gather row idx[2s+h] (index via shuffle, not L1 writeback)
        const int r = __shfl_sync(FULLMASK, myidx, 2 * s + h);
        const ulonglong2 fv = featq[(size_t)r * 16];   // row stride 256B
        gx = add2(gx, fv.x);
        gy = add2(gy, fv.y);

        // MLP for k = 2s+h, two packed channel pairs
        const unsigned long long g0 = pk2(v.x, v.x);
        const unsigned long long g1 = pk2(v.y, v.y);
        const unsigned long long g2 = pk2(v.z, v.z);
        const unsigned long long g3 = pk2(v.w, v.w);

        unsigned long long t0 = fma2(g0, w00, bP0);
        t0 = fma2(g1, w01, t0); t0 = fma2(g2, w02, t0); t0 = fma2(g3, w03, t0);
        accP0 = fma2(t0, c055, accP0);
        accP0 = fma2(t0 & ABSM, c045, accP0);

        unsigned long long t1 = fma2(g0, w10, bP1);
        t1 = fma2(g1, w11, t1); t1 = fma2(g2, w12, t1); t1 = fma2(g3, w13, t1);
        accP1 = fma2(t1, c055, accP1);
        accP1 = fma2(t1 & ABSM, c045, accP1);
    }

    // ---- combine k-halves and write MLP output ----
    const unsigned long long inv = pk2(0.0625f, 0.0625f);
    accP0 = mul2(add2(accP0, shflxor16(accP0)), inv);
    accP1 = mul2(add2(accP1, shflxor16(accP1)), inv);

    float p0l, p0h, p1l, p1h;
    upk2(accP0, p0l, p0h);        // (ch c,    ch c+32)
    upk2(accP1, p1l, p1h);        // (ch c+16, ch c+48)

    const size_t ob = (size_t)p * 128;
    float* o0 = out + ob + c + 32 * h;        // half 0: {c,c+16}; half 1: {c+32,c+48}
    o0[0]  = h ? p0h : p0l;
    o0[16] = h ? p1h : p1l;

    // ---- combine gather halves, write [64,128) ----
    const unsigned long long ox = __shfl_down_sync(FULLMASK, gx, 16);
    const unsigned long long oy = __shfl_down_sync(FULLMASK, gy, 16);
    if (lane < 16) {
        ulonglong2 res;
        res.x = mul2(add2(gx, ox), inv);
        res.y = mul2(add2(gy, oy), inv);
        ((ulonglong2*)(out + ob + 64))[c] = res;
    }
}

extern "C" void kernel_launch(void* const* d_in, const int* in_sizes, int n_in,
                              void* d_out, int out_size) {
    const float* features    = (const float*)d_in[0];
    const float* geom        = (const float*)d_in[1];
    const float* w           = (const float*)d_in[2];
    const float* bias        = (const float*)d_in[3];
    const int*   nbr         = (const int*)d_in[4];    // int32 (JAX x64 off)
    float* out               = (float*)d_out;

    const int points = in_sizes[0] / 64;          // B*N = 65536
    const int n_log2 = 14;                        // N = 16384 per batch

    const int blocks = (points + 3) / 4;          // 4 warps/block, 1 point/warp
    (void)n_in; (void)out_size;
    lfa_kernel<<<blocks, 128>>>(features, (const float4*)geom, w, bias, nbr,
                                out, points, n_log2);
}